// round 2
// baseline (speedup 1.0000x reference)
#include <cuda_runtime.h>
#include <cuda_bf16.h>

// GAT: B=4, N=4096, C=64
// out = elu( softmax_j( mask(adj>0.5, lrelu(s1_i + s2_j)) ) @ h )
// No max-subtraction needed: |e| small enough that exp() stays in fp32 range.

#define GB 4
#define GN 4096
#define GC 64
#define TI 64
#define TJ 64
#define ALPHA 0.2f
#define THRESH 0.5f

__device__ float g_s1[GB * GN];
__device__ float g_s2[GB * GN];

// ---------------------------------------------------------------------------
// Kernel 1: s1[b,n] = h[b,n,:]·a[0:64],  s2[b,n] = h[b,n,:]·a[64:128]
// One warp per row. 2048 blocks x 256 threads (8 warps/block).
// ---------------------------------------------------------------------------
__global__ void gat_scores_kernel(const float* __restrict__ h,
                                  const float* __restrict__ a) {
    int warp = (blockIdx.x * blockDim.x + threadIdx.x) >> 5;
    int lane = threadIdx.x & 31;
    if (warp >= GB * GN) return;
    const float* row = h + (size_t)warp * GC;
    float v0 = row[lane];
    float v1 = row[lane + 32];
    float p1 = v0 * a[lane]      + v1 * a[lane + 32];
    float p2 = v0 * a[GC + lane] + v1 * a[GC + lane + 32];
#pragma unroll
    for (int o = 16; o; o >>= 1) {
        p1 += __shfl_xor_sync(0xFFFFFFFFu, p1, o);
        p2 += __shfl_xor_sync(0xFFFFFFFFu, p2, o);
    }
    if (lane == 0) {
        g_s1[warp] = p1;
        g_s2[warp] = p2;
    }
}

// ---------------------------------------------------------------------------
// Kernel 2: fused masked-softmax + aggregation.
// Grid: (N/TI, B) = (64, 4). Block: 256 threads.
// Per block: 64 i-rows of one batch. Loop over 64-wide j tiles:
//   phase A: load h tile + s2 tile to smem
//   phase B: w[i][j] = adj>0.5 ? exp(lrelu(s1_i+s2_j)) : 0  (+ row sums -> sh_l)
//   phase C: 64x64x64 GEMM: acc[i][c] += w[i][j] * h[j][c]
// Epilogue: out = elu(acc / l)
// ---------------------------------------------------------------------------
__global__ __launch_bounds__(256, 2)
void gat_main_kernel(const float* __restrict__ h,
                     const float* __restrict__ adj,
                     float* __restrict__ out) {
    __shared__ float sh_h[TJ][GC];    // 16 KB
    __shared__ float sh_w[TI][TJ];    // 16 KB
    __shared__ float sh_s1[TI];
    __shared__ float sh_s2[TJ];
    __shared__ float sh_l[TI];

    const int b  = blockIdx.y;
    const int i0 = blockIdx.x * TI;
    const int t  = threadIdx.x;
    const int tx = t & 15;    // c-group: c0 = tx*4
    const int ty = t >> 4;    // i-group: i_local = ty*4 .. +3

    const float* hb = h + (size_t)b * GN * GC;

    if (t < TI) {
        sh_s1[t] = g_s1[b * GN + i0 + t];
        sh_l[t]  = 0.0f;
    }

    float acc[4][4] = {};

    __syncthreads();

    const float LOG2E = 1.4426950408889634f;

    for (int j0 = 0; j0 < GN; j0 += TJ) {
        // ---- phase A: load tiles ----
        if (t < TJ) sh_s2[t] = g_s2[b * GN + j0 + t];
        {
            const float4* hsrc = (const float4*)(hb + (size_t)j0 * GC);
            float4* hdst = (float4*)&sh_h[0][0];
#pragma unroll
            for (int k = 0; k < 4; k++)
                hdst[t + 256 * k] = hsrc[t + 256 * k];
        }
        __syncthreads();

        // ---- phase B: compute weights + row sums ----
#pragma unroll
        for (int k = 0; k < 16; k++) {
            int idx = t + 256 * k;
            int jj = idx & 63;
            int ii = idx >> 6;
            float aval = adj[(size_t)(i0 + ii) * GN + (j0 + jj)];
            float e = sh_s1[ii] + sh_s2[jj];
            e = fmaxf(e, ALPHA * e);              // leaky relu (alpha < 1)
            float w = (aval > THRESH) ? exp2f(e * LOG2E) : 0.0f;
            sh_w[ii][jj] = w;
            // warp rowsum: all 32 lanes of a warp share ii (consecutive jj)
            float ws = w;
#pragma unroll
            for (int o = 16; o; o >>= 1)
                ws += __shfl_xor_sync(0xFFFFFFFFu, ws, o);
            if ((t & 31) == 0) atomicAdd(&sh_l[ii], ws);
        }
        __syncthreads();

        // ---- phase C: GEMM acc[i][c] += w[i][j]*h[j][c] ----
#pragma unroll 8
        for (int jj = 0; jj < TJ; jj++) {
            float4 hv = *(const float4*)&sh_h[jj][tx * 4];
            float hreg[4] = {hv.x, hv.y, hv.z, hv.w};
            float wreg[4];
#pragma unroll
            for (int ii = 0; ii < 4; ii++)
                wreg[ii] = sh_w[ty * 4 + ii][jj];
#pragma unroll
            for (int ii = 0; ii < 4; ii++)
#pragma unroll
                for (int cc = 0; cc < 4; cc++)
                    acc[ii][cc] = fmaf(wreg[ii], hreg[cc], acc[ii][cc]);
        }
        __syncthreads();   // protect sh_h/sh_w before next tile overwrites
    }

    // ---- epilogue: normalize + ELU + store ----
#pragma unroll
    for (int ii = 0; ii < 4; ii++) {
        int i = ty * 4 + ii;
        float linv = 1.0f / sh_l[i];
        float4 o4;
        float v;
        v = acc[ii][0] * linv; o4.x = (v > 0.0f) ? v : expm1f(v);
        v = acc[ii][1] * linv; o4.y = (v > 0.0f) ? v : expm1f(v);
        v = acc[ii][2] * linv; o4.z = (v > 0.0f) ? v : expm1f(v);
        v = acc[ii][3] * linv; o4.w = (v > 0.0f) ? v : expm1f(v);
        size_t oidx = ((size_t)b * GN + (i0 + i)) * GC + tx * 4;
        *(float4*)(out + oidx) = o4;
    }
}

// ---------------------------------------------------------------------------
extern "C" void kernel_launch(void* const* d_in, const int* in_sizes, int n_in,
                              void* d_out, int out_size) {
    const float* input = (const float*)d_in[0];   // (B, N, C)
    const float* adj   = (const float*)d_in[1];   // (N, N)
    const float* a     = (const float*)d_in[2];   // (2C, 1)
    float* out = (float*)d_out;                   // (B, N, C)

    // scores: B*N rows, 1 warp/row, 8 warps/block
    gat_scores_kernel<<<(GB * GN) / 8, 256>>>(input, a);

    dim3 grid(GN / TI, GB);
    gat_main_kernel<<<grid, 256>>>(input, adj, out);
}

// round 3
// speedup vs baseline: 1.3793x; 1.3793x over previous
#include <cuda_runtime.h>
#include <cuda_bf16.h>

// GAT: B=4, N=4096, C=64
// out = elu( softmax_j( mask(adj>0.5, lrelu(s1_i + s2_j)) ) @ h )
// Single-pass softmax (no max-subtraction needed: scores are small).
// R3: drop shuffle/atomic rowsum (accumulate l in phase C), vectorize w loads,
//     use packed fma.rn.f32x2 (FFMA2) for the PV accumulation.

#define GB 4
#define GN 4096
#define GC 64
#define TI 64
#define TJ 64
#define ALPHA 0.2f
#define THRESH 0.5f

__device__ float g_s1[GB * GN];
__device__ float g_s2[GB * GN];

#define FMA_F32X2(d, a, b) \
    asm("fma.rn.f32x2 %0, %1, %2, %0;" : "+l"(d) : "l"(a), "l"(b))
#define PACK2(out, lo, hi) \
    asm("mov.b64 %0, {%1, %2};" : "=l"(out) : "f"(lo), "f"(hi))
#define PACK2S(out, v) \
    asm("mov.b64 %0, {%1, %1};" : "=l"(out) : "f"(v))
#define UNPACK2(lo, hi, in) \
    asm("mov.b64 {%0, %1}, %2;" : "=f"(lo), "=f"(hi) : "l"(in))

// ---------------------------------------------------------------------------
// Kernel 1: s1[b,n] = h[b,n,:]·a[0:64],  s2[b,n] = h[b,n,:]·a[64:128]
// ---------------------------------------------------------------------------
__global__ void gat_scores_kernel(const float* __restrict__ h,
                                  const float* __restrict__ a) {
    int warp = (blockIdx.x * blockDim.x + threadIdx.x) >> 5;
    int lane = threadIdx.x & 31;
    if (warp >= GB * GN) return;
    const float* row = h + (size_t)warp * GC;
    float v0 = row[lane];
    float v1 = row[lane + 32];
    float p1 = v0 * a[lane]      + v1 * a[lane + 32];
    float p2 = v0 * a[GC + lane] + v1 * a[GC + lane + 32];
#pragma unroll
    for (int o = 16; o; o >>= 1) {
        p1 += __shfl_xor_sync(0xFFFFFFFFu, p1, o);
        p2 += __shfl_xor_sync(0xFFFFFFFFu, p2, o);
    }
    if (lane == 0) {
        g_s1[warp] = p1;
        g_s2[warp] = p2;
    }
}

// ---------------------------------------------------------------------------
// Kernel 2: fused masked-softmax + aggregation.
// Grid: (N/TI, B) = (64, 4). Block: 256 threads, 4x4 micro-tile (C packed x2).
// ---------------------------------------------------------------------------
__global__ __launch_bounds__(256, 2)
void gat_main_kernel(const float* __restrict__ h,
                     const float* __restrict__ adj,
                     float* __restrict__ out) {
    __shared__ float sh_h[TJ][GC];    // 16 KB
    __shared__ float sh_w[TI][TJ];    // 16 KB
    __shared__ float sh_s1[TI];
    __shared__ float sh_s2[TJ];
    __shared__ float sh_l[TI];

    const int b  = blockIdx.y;
    const int i0 = blockIdx.x * TI;
    const int t  = threadIdx.x;
    const int tx = t & 15;    // c-group: c0 = tx*4
    const int ty = t >> 4;    // i-group: i_local = ty*4 .. +3

    const float* hb = h + (size_t)b * GN * GC;

    if (t < TI) sh_s1[t] = g_s1[b * GN + i0 + t];

    unsigned long long acc[4][2];     // 4 rows x (4 C-values packed as 2 f32x2)
#pragma unroll
    for (int ii = 0; ii < 4; ii++) { acc[ii][0] = 0ull; acc[ii][1] = 0ull; }
    float lacc[4] = {0.f, 0.f, 0.f, 0.f};

    __syncthreads();

    const float LOG2E = 1.4426950408889634f;

    for (int j0 = 0; j0 < GN; j0 += TJ) {
        // ---- phase A: load h tile + s2 ----
        if (t < TJ) sh_s2[t] = g_s2[b * GN + j0 + t];
        {
            const float4* hsrc = (const float4*)(hb + (size_t)j0 * GC);
            float4* hdst = (float4*)&sh_h[0][0];
#pragma unroll
            for (int k = 0; k < 4; k++)
                hdst[t + 256 * k] = hsrc[t + 256 * k];
        }
        __syncthreads();

        // ---- phase B: w[i][j] = adj>0.5 ? exp(lrelu(s1+s2)) : 0 ----
#pragma unroll
        for (int k = 0; k < 4; k++) {
            int flat = k * 1024 + t * 4;
            int ii = flat >> 6;
            int jj = flat & 63;
            float4 av = *(const float4*)&adj[(size_t)(i0 + ii) * GN + j0 + jj];
            float s1v = sh_s1[ii];
            float4 w4;
            {
                float e = s1v + sh_s2[jj + 0];
                e = fmaxf(e, ALPHA * e);
                w4.x = (av.x > THRESH) ? exp2f(e * LOG2E) : 0.0f;
            }
            {
                float e = s1v + sh_s2[jj + 1];
                e = fmaxf(e, ALPHA * e);
                w4.y = (av.y > THRESH) ? exp2f(e * LOG2E) : 0.0f;
            }
            {
                float e = s1v + sh_s2[jj + 2];
                e = fmaxf(e, ALPHA * e);
                w4.z = (av.z > THRESH) ? exp2f(e * LOG2E) : 0.0f;
            }
            {
                float e = s1v + sh_s2[jj + 3];
                e = fmaxf(e, ALPHA * e);
                w4.w = (av.w > THRESH) ? exp2f(e * LOG2E) : 0.0f;
            }
            *(float4*)&sh_w[ii][jj] = w4;
        }
        __syncthreads();

        // ---- phase C: acc[i][c] += w[i][j]*h[j][c]  (packed f32x2) ----
#pragma unroll 4
        for (int jc = 0; jc < TJ; jc += 4) {
            float4 w4[4];
#pragma unroll
            for (int ii = 0; ii < 4; ii++)
                w4[ii] = *(const float4*)&sh_w[ty * 4 + ii][jc];

            if (tx == 0) {
#pragma unroll
                for (int ii = 0; ii < 4; ii++)
                    lacc[ii] += (w4[ii].x + w4[ii].y) + (w4[ii].z + w4[ii].w);
            }

#pragma unroll
            for (int u = 0; u < 4; u++) {
                float4 hv = *(const float4*)&sh_h[jc + u][tx * 4];
                unsigned long long h01, h23;
                PACK2(h01, hv.x, hv.y);
                PACK2(h23, hv.z, hv.w);
#pragma unroll
                for (int ii = 0; ii < 4; ii++) {
                    float w = (u == 0) ? w4[ii].x : (u == 1) ? w4[ii].y
                            : (u == 2) ? w4[ii].z : w4[ii].w;
                    unsigned long long wp;
                    PACK2S(wp, w);
                    FMA_F32X2(acc[ii][0], wp, h01);
                    FMA_F32X2(acc[ii][1], wp, h23);
                }
            }
        }
        __syncthreads();   // protect sh_h/sh_w before next tile overwrites
    }

    // ---- epilogue: share row sums, normalize + ELU + store ----
    if (tx == 0) {
#pragma unroll
        for (int ii = 0; ii < 4; ii++)
            sh_l[ty * 4 + ii] = lacc[ii];
    }
    __syncthreads();

#pragma unroll
    for (int ii = 0; ii < 4; ii++) {
        int i = ty * 4 + ii;
        float linv = 1.0f / sh_l[i];
        float a0, a1, a2, a3;
        UNPACK2(a0, a1, acc[ii][0]);
        UNPACK2(a2, a3, acc[ii][1]);
        float4 o4;
        float v;
        v = a0 * linv; o4.x = (v > 0.0f) ? v : expm1f(v);
        v = a1 * linv; o4.y = (v > 0.0f) ? v : expm1f(v);
        v = a2 * linv; o4.z = (v > 0.0f) ? v : expm1f(v);
        v = a3 * linv; o4.w = (v > 0.0f) ? v : expm1f(v);
        size_t oidx = ((size_t)b * GN + (i0 + i)) * GC + tx * 4;
        *(float4*)(out + oidx) = o4;
    }
}

// ---------------------------------------------------------------------------
extern "C" void kernel_launch(void* const* d_in, const int* in_sizes, int n_in,
                              void* d_out, int out_size) {
    const float* input = (const float*)d_in[0];   // (B, N, C)
    const float* adj   = (const float*)d_in[1];   // (N, N)
    const float* a     = (const float*)d_in[2];   // (2C, 1)
    float* out = (float*)d_out;                   // (B, N, C)

    gat_scores_kernel<<<(GB * GN) / 8, 256>>>(input, a);

    dim3 grid(GN / TI, GB);
    gat_main_kernel<<<grid, 256>>>(input, adj, out);
}

// round 5
// speedup vs baseline: 2.4438x; 1.7718x over previous
#include <cuda_runtime.h>
#include <cuda_bf16.h>
#include <cstdint>

// GAT: B=4, N=4096, C=64
// out = elu( softmax_j( mask(adj>0.5, lrelu(s1+s2)) ) @ h )
// R5: mma.sync bf16 (baseline PTX, works on compute_103) 3-term hi/lo split,
//     cp.async double-buffered adj/h pipeline, ldmatrix-fed HMMA.

#define GB 4
#define GN 4096
#define GC 64
#define TI 128
#define TJ 64
#define NTILES (GN / TJ)
#define ALPHA 0.2f
#define THRESH 0.5f

// dynamic smem per-stage layout
#define ADJ_OFF 0         // 128 x 64 fp32          (32 KB)
#define WH_OFF  32768     // 128 rows x 128B bf16   (16 KB)
#define WL_OFF  49152     // 128 rows x 128B bf16   (16 KB)
#define BH_OFF  65536     // 64 rows x 128B bf16    ( 8 KB)
#define BL_OFF  73728     // 64 rows x 128B bf16    ( 8 KB)
#define STAGE   81920
#define DSMEM_BYTES (2 * STAGE + 1024)

__device__ float g_s1[GB * GN];
__device__ float g_s2[GB * GN];
__device__ __nv_bfloat16 g_hh[GB * GN * GC];
__device__ __nv_bfloat16 g_hl[GB * GN * GC];

// ---------------------------------------------------------------- helpers
static __device__ __forceinline__ uint32_t smem_u32(const void* p) {
    uint32_t a;
    asm("{ .reg .u64 t; cvta.to.shared.u64 t, %1; cvt.u32.u64 %0, t; }"
        : "=r"(a) : "l"(p));
    return a;
}
static __device__ __forceinline__ float fast_ex2(float x) {
    float r; asm("ex2.approx.f32 %0, %1;" : "=f"(r) : "f"(x)); return r;
}
// packs {lo -> low16, hi -> high16}
static __device__ __forceinline__ uint32_t cvt_bf16x2(float lo, float hi) {
    uint32_t r;
    asm("cvt.rn.bf16x2.f32 %0, %1, %2;" : "=r"(r) : "f"(hi), "f"(lo));
    return r;
}
static __device__ __forceinline__ uint32_t sw128(uint32_t b) {
    return b ^ ((b >> 3) & 0x70);
}
#define CP16(dst, src) \
    asm volatile("cp.async.cg.shared.global [%0], [%1], 16;" \
                 :: "r"(dst), "l"(src) : "memory")
#define CP_COMMIT() asm volatile("cp.async.commit_group;" ::: "memory")
#define CP_WAIT1()  asm volatile("cp.async.wait_group 1;" ::: "memory")

static __device__ __forceinline__ void ldmx4(uint32_t* r, uint32_t addr) {
    asm volatile("ldmatrix.sync.aligned.m8n8.x4.shared.b16 {%0,%1,%2,%3}, [%4];"
        : "=r"(r[0]), "=r"(r[1]), "=r"(r[2]), "=r"(r[3]) : "r"(addr));
}
static __device__ __forceinline__ void ldmx4t(uint32_t* r, uint32_t addr) {
    asm volatile("ldmatrix.sync.aligned.m8n8.x4.trans.shared.b16 {%0,%1,%2,%3}, [%4];"
        : "=r"(r[0]), "=r"(r[1]), "=r"(r[2]), "=r"(r[3]) : "r"(addr));
}
static __device__ __forceinline__ void mma_bf16(float* d, const uint32_t* a,
                                                uint32_t b0, uint32_t b1) {
    asm volatile(
        "mma.sync.aligned.m16n8k16.row.col.f32.bf16.bf16.f32 "
        "{%0,%1,%2,%3}, {%4,%5,%6,%7}, {%8,%9}, {%0,%1,%2,%3};"
        : "+f"(d[0]), "+f"(d[1]), "+f"(d[2]), "+f"(d[3])
        : "r"(a[0]), "r"(a[1]), "r"(a[2]), "r"(a[3]), "r"(b0), "r"(b1));
}

// ---------------------------------------------------------------- kernel 1
// s1/s2 (pre-scaled by log2e) + h hi/lo bf16 split.
__global__ void gat_scores_kernel(const float* __restrict__ h,
                                  const float* __restrict__ a) {
    int warp = (blockIdx.x * blockDim.x + threadIdx.x) >> 5;
    int lane = threadIdx.x & 31;
    if (warp >= GB * GN) return;
    const float* row = h + (size_t)warp * GC;
    float v0 = row[lane];
    float v1 = row[lane + 32];

    __nv_bfloat16 h0 = __float2bfloat16_rn(v0);
    __nv_bfloat16 h1 = __float2bfloat16_rn(v1);
    g_hh[warp * GC + lane]      = h0;
    g_hh[warp * GC + lane + 32] = h1;
    g_hl[warp * GC + lane]      = __float2bfloat16_rn(v0 - __bfloat162float(h0));
    g_hl[warp * GC + lane + 32] = __float2bfloat16_rn(v1 - __bfloat162float(h1));

    float p1 = v0 * a[lane]      + v1 * a[lane + 32];
    float p2 = v0 * a[GC + lane] + v1 * a[GC + lane + 32];
#pragma unroll
    for (int o = 16; o; o >>= 1) {
        p1 += __shfl_xor_sync(0xFFFFFFFFu, p1, o);
        p2 += __shfl_xor_sync(0xFFFFFFFFu, p2, o);
    }
    const float LOG2E = 1.4426950408889634f;
    if (lane == 0) {
        g_s1[warp] = p1 * LOG2E;
        g_s2[warp] = p2 * LOG2E;
    }
}

// ---------------------------------------------------------------- prefetch
static __device__ __forceinline__ void prefetch_tile(uint32_t stg,
                                                     const float* __restrict__ adj,
                                                     int b, int i0, int j0, int t) {
#pragma unroll
    for (int k = 0; k < 8; k++) {
        int q = t + 256 * k;
        int ii = q >> 4, cc = q & 15;
        const float* src = adj + (size_t)(i0 + ii) * GN + j0 + cc * 4;
        CP16(stg + ADJ_OFF + ii * 256 + cc * 16, src);
    }
    const __nv_bfloat16* hh = g_hh + ((size_t)b * GN + j0) * GC;
    const __nv_bfloat16* hl = g_hl + ((size_t)b * GN + j0) * GC;
#pragma unroll
    for (int k = 0; k < 2; k++) {
        int q = t + 256 * k;
        int j = q >> 3, cc = q & 7;
        uint32_t off = sw128((uint32_t)(j * 128 + cc * 16));
        CP16(stg + BH_OFF + off, hh + j * GC + cc * 8);
        CP16(stg + BL_OFF + off, hl + j * GC + cc * 8);
    }
}

// ---------------------------------------------------------------- kernel 2
__global__ __launch_bounds__(256, 1)
void gat_main_kernel(const float* __restrict__ adj,
                     float* __restrict__ out) {
    extern __shared__ char smem_raw[];
    __shared__ float sh_l[TI];

    const int t    = threadIdx.x;
    const int wid  = t >> 5;
    const int lane = t & 31;
    const int b    = blockIdx.y;
    const int i0   = blockIdx.x * TI;

    uint32_t raw_u32 = smem_u32(smem_raw);
    uint32_t sbu = (raw_u32 + 1023u) & ~1023u;

    if (t < TI) sh_l[t] = 0.0f;

    // phase-B mapping
    const int r0  = t >> 4;
    const int jj0 = (t & 15) * 4;
    float s1r[8];
#pragma unroll
    for (int k = 0; k < 8; k++)
        s1r[k] = g_s1[b * GN + i0 + r0 + 16 * k];
    float lsum[8] = {0.f, 0.f, 0.f, 0.f, 0.f, 0.f, 0.f, 0.f};

    // ldmatrix per-lane constants
    const uint32_t xr     = (uint32_t)(lane & 7) << 4;              // swizzle XOR
    const uint32_t a_base = (uint32_t)((wid * 16 + (lane & 15)) * 128 + (lane & 16));
    const uint32_t b_base = (uint32_t)((lane & 15) * 128 + (lane & 16));

    float acc[8][4];
#pragma unroll
    for (int nn = 0; nn < 8; nn++)
#pragma unroll
        for (int q = 0; q < 4; q++) acc[nn][q] = 0.0f;

    // prologue prefetch of tile 0 into stage 0
    prefetch_tile(sbu, adj, b, i0, 0, t);
    CP_COMMIT();

    for (int tile = 0; tile < NTILES; tile++) {
        const int s = tile & 1;
        const uint32_t stg = sbu + s * STAGE;
        const int j0 = tile * TJ;

        __syncthreads();   // mma(tile-1) done: stage s^1 free for prefetch

        if (tile + 1 < NTILES)
            prefetch_tile(sbu + (s ^ 1) * STAGE, adj, b, i0, j0 + TJ, t);
        CP_COMMIT();
        CP_WAIT1();        // tile's own group complete
        __syncthreads();   // make cp.async data visible to all threads

        // ---- phase B: w tile (hi/lo bf16, K-major, SW128) ----
        {
            float4 s2v = *(const float4*)&g_s2[b * GN + j0 + jj0];
#pragma unroll
            for (int k = 0; k < 8; k++) {
                int ii = r0 + 16 * k;
                float4 av;
                {
                    uint32_t aaddr = stg + ADJ_OFF + ii * 256 + jj0 * 4;
                    asm volatile("ld.shared.v4.f32 {%0,%1,%2,%3}, [%4];"
                                 : "=f"(av.x), "=f"(av.y), "=f"(av.z), "=f"(av.w)
                                 : "r"(aaddr));
                }
                float e0 = s1r[k] + s2v.x; e0 = fmaxf(e0, ALPHA * e0);
                float e1 = s1r[k] + s2v.y; e1 = fmaxf(e1, ALPHA * e1);
                float e2 = s1r[k] + s2v.z; e2 = fmaxf(e2, ALPHA * e2);
                float e3 = s1r[k] + s2v.w; e3 = fmaxf(e3, ALPHA * e3);
                float w0 = (av.x > THRESH) ? fast_ex2(e0) : 0.0f;
                float w1 = (av.y > THRESH) ? fast_ex2(e1) : 0.0f;
                float w2 = (av.z > THRESH) ? fast_ex2(e2) : 0.0f;
                float w3 = (av.w > THRESH) ? fast_ex2(e3) : 0.0f;
                lsum[k] += (w0 + w1) + (w2 + w3);
                uint32_t h01 = cvt_bf16x2(w0, w1);
                uint32_t h23 = cvt_bf16x2(w2, w3);
                float f0 = __uint_as_float(h01 << 16);
                float f1 = __uint_as_float(h01 & 0xFFFF0000u);
                float f2 = __uint_as_float(h23 << 16);
                float f3 = __uint_as_float(h23 & 0xFFFF0000u);
                uint32_t l01 = cvt_bf16x2(w0 - f0, w1 - f1);
                uint32_t l23 = cvt_bf16x2(w2 - f2, w3 - f3);
                uint32_t off = sw128((uint32_t)(ii * 128 + jj0 * 2));
                uint32_t dh = stg + WH_OFF + off;
                uint32_t dl = stg + WL_OFF + off;
                asm volatile("st.shared.v2.b32 [%0], {%1,%2};"
                             :: "r"(dh), "r"(h01), "r"(h23) : "memory");
                asm volatile("st.shared.v2.b32 [%0], {%1,%2};"
                             :: "r"(dl), "r"(l01), "r"(l23) : "memory");
            }
        }
        __syncthreads();

        // ---- MMA phase: 3-term bf16 ----
        {
            const uint32_t whb = stg + WH_OFF;
            const uint32_t wlb = stg + WL_OFF;
            const uint32_t bhb = stg + BH_OFF;
            const uint32_t blb = stg + BL_OFF;
#pragma unroll
            for (int kk = 0; kk < 4; kk++) {
                uint32_t ahi[4], alo[4];
                uint32_t a_off = (a_base + kk * 32) ^ xr;
                ldmx4(ahi, whb + a_off);
                ldmx4(alo, wlb + a_off);
                uint32_t bh[16], bl[16];
#pragma unroll
                for (int np = 0; np < 4; np++) {
                    uint32_t b_off = (b_base + kk * 2048 + np * 32) ^ xr;
                    ldmx4t(&bh[np * 4], bhb + b_off);
                    ldmx4t(&bl[np * 4], blb + b_off);
                }
#pragma unroll
                for (int nn = 0; nn < 8; nn++) {
                    int base = (nn >> 1) * 4 + (nn & 1) * 2;
                    mma_bf16(acc[nn], ahi, bh[base], bh[base + 1]);
                    mma_bf16(acc[nn], ahi, bl[base], bl[base + 1]);
                    mma_bf16(acc[nn], alo, bh[base], bh[base + 1]);
                }
            }
        }
    }

    // ---- row sums ----
#pragma unroll
    for (int k = 0; k < 8; k++)
        atomicAdd(&sh_l[r0 + 16 * k], lsum[k]);
    __syncthreads();

    // ---- epilogue: normalize + ELU + store ----
    {
        int g  = lane >> 2;
        int qc = (lane & 3) * 2;
        int ra = wid * 16 + g;
        int rb = ra + 8;
        float la = 1.0f / sh_l[ra];
        float lb = 1.0f / sh_l[rb];
        float* oa = out + ((size_t)b * GN + i0 + ra) * GC;
        float* ob = out + ((size_t)b * GN + i0 + rb) * GC;
#pragma unroll
        for (int nn = 0; nn < 8; nn++) {
            int c = nn * 8 + qc;
            float v0 = acc[nn][0] * la, v1 = acc[nn][1] * la;
            float v2 = acc[nn][2] * lb, v3 = acc[nn][3] * lb;
            float2 pa, pb;
            pa.x = (v0 > 0.f) ? v0 : expm1f(v0);
            pa.y = (v1 > 0.f) ? v1 : expm1f(v1);
            pb.x = (v2 > 0.f) ? v2 : expm1f(v2);
            pb.y = (v3 > 0.f) ? v3 : expm1f(v3);
            *(float2*)(oa + c) = pa;
            *(float2*)(ob + c) = pb;
        }
    }
}

// ---------------------------------------------------------------- launch
extern "C" void kernel_launch(void* const* d_in, const int* in_sizes, int n_in,
                              void* d_out, int out_size) {
    const float* input = (const float*)d_in[0];   // (B, N, C)
    const float* adj   = (const float*)d_in[1];   // (N, N)
    const float* a     = (const float*)d_in[2];   // (2C, 1)
    float* out = (float*)d_out;                   // (B, N, C)

    gat_scores_kernel<<<(GB * GN) / 8, 256>>>(input, a);

    cudaFuncSetAttribute(gat_main_kernel,
                         cudaFuncAttributeMaxDynamicSharedMemorySize, DSMEM_BYTES);
    dim3 grid(GN / TI, GB);
    gat_main_kernel<<<grid, 256, DSMEM_BYTES>>>(adj, out);
}

// round 6
// speedup vs baseline: 3.6130x; 1.4784x over previous
#include <cuda_runtime.h>
#include <cuda_bf16.h>
#include <cstdint>

// GAT: B=4, N=4096, C=64
// out = elu( softmax_j( mask(adj>0.5, lrelu(s1+s2)) ) @ h )
// R6: TI=64, 2 CTAs/SM, 4x2 warp tiling, 2 barriers/tile, prefetch under MMA.

#define GB 4
#define GN 4096
#define GC 64
#define TI 64
#define TJ 64
#define NTILES (GN / TJ)
#define ALPHA 0.2f
#define THRESH 0.5f

// per-stage smem layout
#define ADJ_OFF 0         // 64 x 64 fp32           (16 KB)
#define WH_OFF  16384     // 64 rows x 128B bf16    ( 8 KB)
#define WL_OFF  24576     // 64 rows x 128B bf16    ( 8 KB)
#define BH_OFF  32768     // 64 rows x 128B bf16    ( 8 KB)
#define BL_OFF  40960     // 64 rows x 128B bf16    ( 8 KB)
#define STAGE   49152
#define DSMEM_BYTES (2 * STAGE + 1024)

__device__ float g_s1[GB * GN];
__device__ float g_s2[GB * GN];
__device__ __nv_bfloat16 g_hh[GB * GN * GC];
__device__ __nv_bfloat16 g_hl[GB * GN * GC];

// ---------------------------------------------------------------- helpers
static __device__ __forceinline__ uint32_t smem_u32(const void* p) {
    uint32_t a;
    asm("{ .reg .u64 t; cvta.to.shared.u64 t, %1; cvt.u32.u64 %0, t; }"
        : "=r"(a) : "l"(p));
    return a;
}
static __device__ __forceinline__ float fast_ex2(float x) {
    float r; asm("ex2.approx.f32 %0, %1;" : "=f"(r) : "f"(x)); return r;
}
// packs {lo -> low16, hi -> high16}
static __device__ __forceinline__ uint32_t cvt_bf16x2(float lo, float hi) {
    uint32_t r;
    asm("cvt.rn.bf16x2.f32 %0, %1, %2;" : "=r"(r) : "f"(hi), "f"(lo));
    return r;
}
static __device__ __forceinline__ uint32_t sw128(uint32_t b) {
    return b ^ ((b >> 3) & 0x70);
}
#define CP16(dst, src) \
    asm volatile("cp.async.cg.shared.global [%0], [%1], 16;" \
                 :: "r"(dst), "l"(src) : "memory")
#define CP_COMMIT() asm volatile("cp.async.commit_group;" ::: "memory")
#define CP_WAIT0()  asm volatile("cp.async.wait_group 0;" ::: "memory")

static __device__ __forceinline__ void ldmx4(uint32_t* r, uint32_t addr) {
    asm volatile("ldmatrix.sync.aligned.m8n8.x4.shared.b16 {%0,%1,%2,%3}, [%4];"
        : "=r"(r[0]), "=r"(r[1]), "=r"(r[2]), "=r"(r[3]) : "r"(addr));
}
static __device__ __forceinline__ void ldmx4t(uint32_t* r, uint32_t addr) {
    asm volatile("ldmatrix.sync.aligned.m8n8.x4.trans.shared.b16 {%0,%1,%2,%3}, [%4];"
        : "=r"(r[0]), "=r"(r[1]), "=r"(r[2]), "=r"(r[3]) : "r"(addr));
}
static __device__ __forceinline__ void mma_bf16(float* d, const uint32_t* a,
                                                uint32_t b0, uint32_t b1) {
    asm volatile(
        "mma.sync.aligned.m16n8k16.row.col.f32.bf16.bf16.f32 "
        "{%0,%1,%2,%3}, {%4,%5,%6,%7}, {%8,%9}, {%0,%1,%2,%3};"
        : "+f"(d[0]), "+f"(d[1]), "+f"(d[2]), "+f"(d[3])
        : "r"(a[0]), "r"(a[1]), "r"(a[2]), "r"(a[3]), "r"(b0), "r"(b1));
}

// ---------------------------------------------------------------- kernel 1
__global__ void gat_scores_kernel(const float* __restrict__ h,
                                  const float* __restrict__ a) {
    int warp = (blockIdx.x * blockDim.x + threadIdx.x) >> 5;
    int lane = threadIdx.x & 31;
    if (warp >= GB * GN) return;
    const float* row = h + (size_t)warp * GC;
    float v0 = row[lane];
    float v1 = row[lane + 32];

    __nv_bfloat16 h0 = __float2bfloat16_rn(v0);
    __nv_bfloat16 h1 = __float2bfloat16_rn(v1);
    g_hh[warp * GC + lane]      = h0;
    g_hh[warp * GC + lane + 32] = h1;
    g_hl[warp * GC + lane]      = __float2bfloat16_rn(v0 - __bfloat162float(h0));
    g_hl[warp * GC + lane + 32] = __float2bfloat16_rn(v1 - __bfloat162float(h1));

    float p1 = v0 * a[lane]      + v1 * a[lane + 32];
    float p2 = v0 * a[GC + lane] + v1 * a[GC + lane + 32];
#pragma unroll
    for (int o = 16; o; o >>= 1) {
        p1 += __shfl_xor_sync(0xFFFFFFFFu, p1, o);
        p2 += __shfl_xor_sync(0xFFFFFFFFu, p2, o);
    }
    const float LOG2E = 1.4426950408889634f;
    if (lane == 0) {
        g_s1[warp] = p1 * LOG2E;
        g_s2[warp] = p2 * LOG2E;
    }
}

// ---------------------------------------------------------------- prefetch
static __device__ __forceinline__ void prefetch_tile(uint32_t stg,
                                                     const float* __restrict__ adj,
                                                     int b, int i0, int j0, int t) {
    // adj tile: 64 x 64 fp32 = 16 KB = 1024 x 16B
#pragma unroll
    for (int k = 0; k < 4; k++) {
        int q = t + 256 * k;
        int ii = q >> 4, cc = q & 15;
        const float* src = adj + (size_t)(i0 + ii) * GN + j0 + cc * 4;
        CP16(stg + ADJ_OFF + ii * 256 + cc * 16, src);
    }
    // h tiles: 64 x 64 bf16 hi + lo, K-major SW128 (rows = j, cols = c)
    const __nv_bfloat16* hh = g_hh + ((size_t)b * GN + j0) * GC;
    const __nv_bfloat16* hl = g_hl + ((size_t)b * GN + j0) * GC;
#pragma unroll
    for (int k = 0; k < 2; k++) {
        int q = t + 256 * k;
        int j = q >> 3, cc = q & 7;
        uint32_t off = sw128((uint32_t)(j * 128 + cc * 16));
        CP16(stg + BH_OFF + off, hh + j * GC + cc * 8);
        CP16(stg + BL_OFF + off, hl + j * GC + cc * 8);
    }
}

// ---------------------------------------------------------------- kernel 2
__global__ __launch_bounds__(256, 2)
void gat_main_kernel(const float* __restrict__ adj,
                     float* __restrict__ out) {
    extern __shared__ char smem_raw[];
    __shared__ float sh_l[TI];

    const int t    = threadIdx.x;
    const int wid  = t >> 5;
    const int lane = t & 31;
    const int b    = blockIdx.y;
    const int i0   = blockIdx.x * TI;
    const int wm   = wid & 3;    // M group: rows wm*16 .. +15
    const int wn   = wid >> 2;   // N group: cols wn*32 .. +31

    uint32_t raw_u32 = smem_u32(smem_raw);
    uint32_t sbu = (raw_u32 + 1023u) & ~1023u;

    if (t < TI) sh_l[t] = 0.0f;

    // phase-B mapping: rows r0 + 16k (k<4), cols jj0..+3
    const int r0  = t >> 4;
    const int jj0 = (t & 15) * 4;
    float s1r[4];
#pragma unroll
    for (int k = 0; k < 4; k++)
        s1r[k] = g_s1[b * GN + i0 + r0 + 16 * k];
    float lsum[4] = {0.f, 0.f, 0.f, 0.f};

    // ldmatrix per-lane constants
    const uint32_t xr     = (uint32_t)(lane & 7) << 4;
    const uint32_t a_base = (uint32_t)((wm * 16 + (lane & 15)) * 128 + (lane & 16));
    const uint32_t b_base = (uint32_t)((lane & 15) * 128 + (lane & 16) + wn * 64);

    float acc[4][4];
#pragma unroll
    for (int nn = 0; nn < 4; nn++)
#pragma unroll
        for (int q = 0; q < 4; q++) acc[nn][q] = 0.0f;

    // prologue: prefetch tile 0 into stage 0
    prefetch_tile(sbu, adj, b, i0, 0, t);
    CP_COMMIT();

    for (int tile = 0; tile < NTILES; tile++) {
        const int s = tile & 1;
        const uint32_t stg = sbu + s * STAGE;

        CP_WAIT0();        // tile's adj/h group complete
        __syncthreads();   // visibility + all warps done MMA(tile-1)

        // ---- phase B: w tile (hi/lo bf16, K-major, SW128) ----
        {
            float4 s2v = *(const float4*)&g_s2[b * GN + tile * TJ + jj0];
            uint32_t abase = stg + ADJ_OFF + r0 * 256 + jj0 * 4;
            uint32_t wbase = sw128((uint32_t)(r0 * 128 + jj0 * 2));
#pragma unroll
            for (int k = 0; k < 4; k++) {
                float4 av;
                asm volatile("ld.shared.v4.f32 {%0,%1,%2,%3}, [%4];"
                             : "=f"(av.x), "=f"(av.y), "=f"(av.z), "=f"(av.w)
                             : "r"(abase + k * 4096));
                float e0 = s1r[k] + s2v.x; e0 = fmaxf(e0, ALPHA * e0);
                float e1 = s1r[k] + s2v.y; e1 = fmaxf(e1, ALPHA * e1);
                float e2 = s1r[k] + s2v.z; e2 = fmaxf(e2, ALPHA * e2);
                float e3 = s1r[k] + s2v.w; e3 = fmaxf(e3, ALPHA * e3);
                float w0 = (av.x > THRESH) ? fast_ex2(e0) : 0.0f;
                float w1 = (av.y > THRESH) ? fast_ex2(e1) : 0.0f;
                float w2 = (av.z > THRESH) ? fast_ex2(e2) : 0.0f;
                float w3 = (av.w > THRESH) ? fast_ex2(e3) : 0.0f;
                lsum[k] += (w0 + w1) + (w2 + w3);
                uint32_t h01 = cvt_bf16x2(w0, w1);
                uint32_t h23 = cvt_bf16x2(w2, w3);
                float f0 = __uint_as_float(h01 << 16);
                float f1 = __uint_as_float(h01 & 0xFFFF0000u);
                float f2 = __uint_as_float(h23 << 16);
                float f3 = __uint_as_float(h23 & 0xFFFF0000u);
                uint32_t l01 = cvt_bf16x2(w0 - f0, w1 - f1);
                uint32_t l23 = cvt_bf16x2(w2 - f2, w3 - f3);
                asm volatile("st.shared.v2.b32 [%0], {%1,%2};"
                             :: "r"(stg + WH_OFF + wbase + k * 2048),
                                "r"(h01), "r"(h23) : "memory");
                asm volatile("st.shared.v2.b32 [%0], {%1,%2};"
                             :: "r"(stg + WL_OFF + wbase + k * 2048),
                                "r"(l01), "r"(l23) : "memory");
            }
        }
        __syncthreads();

        // ---- prefetch next tile into other stage (overlaps MMA) ----
        if (tile + 1 < NTILES) {
            prefetch_tile(sbu + (s ^ 1) * STAGE, adj, b, i0, (tile + 1) * TJ, t);
            CP_COMMIT();
        }

        // ---- MMA phase: 3-term bf16, warp tile 16x32 ----
        {
            const uint32_t whb = stg + WH_OFF;
            const uint32_t wlb = stg + WL_OFF;
            const uint32_t bhb = stg + BH_OFF;
            const uint32_t blb = stg + BL_OFF;
#pragma unroll
            for (int kk = 0; kk < 4; kk++) {
                uint32_t ahi[4], alo[4];
                uint32_t a_off = (a_base + kk * 32) ^ xr;
                ldmx4(ahi, whb + a_off);
                ldmx4(alo, wlb + a_off);
                uint32_t bh[8], bl[8];
#pragma unroll
                for (int np = 0; np < 2; np++) {
                    uint32_t b_off = (b_base + kk * 2048 + np * 32) ^ xr;
                    ldmx4t(&bh[np * 4], bhb + b_off);
                    ldmx4t(&bl[np * 4], blb + b_off);
                }
#pragma unroll
                for (int nn = 0; nn < 4; nn++) {
                    int base = (nn >> 1) * 4 + (nn & 1) * 2;
                    mma_bf16(acc[nn], ahi, bh[base], bh[base + 1]);
                    mma_bf16(acc[nn], ahi, bl[base], bl[base + 1]);
                    mma_bf16(acc[nn], alo, bh[base], bh[base + 1]);
                }
            }
        }
    }

    // ---- row sums ----
#pragma unroll
    for (int k = 0; k < 4; k++)
        atomicAdd(&sh_l[r0 + 16 * k], lsum[k]);
    __syncthreads();

    // ---- epilogue: normalize + ELU + store ----
    {
        int g  = lane >> 2;
        int qc = (lane & 3) * 2;
        int ra = wm * 16 + g;
        int rb = ra + 8;
        float la = 1.0f / sh_l[ra];
        float lb = 1.0f / sh_l[rb];
        float* oa = out + ((size_t)b * GN + i0 + ra) * GC;
        float* ob = out + ((size_t)b * GN + i0 + rb) * GC;
#pragma unroll
        for (int nn = 0; nn < 4; nn++) {
            int c = wn * 32 + nn * 8 + qc;
            float v0 = acc[nn][0] * la, v1 = acc[nn][1] * la;
            float v2 = acc[nn][2] * lb, v3 = acc[nn][3] * lb;
            float2 pa, pb;
            pa.x = (v0 > 0.f) ? v0 : expm1f(v0);
            pa.y = (v1 > 0.f) ? v1 : expm1f(v1);
            pb.x = (v2 > 0.f) ? v2 : expm1f(v2);
            pb.y = (v3 > 0.f) ? v3 : expm1f(v3);
            *(float2*)(oa + c) = pa;
            *(float2*)(ob + c) = pb;
        }
    }
}

// ---------------------------------------------------------------- launch
extern "C" void kernel_launch(void* const* d_in, const int* in_sizes, int n_in,
                              void* d_out, int out_size) {
    const float* input = (const float*)d_in[0];   // (B, N, C)
    const float* adj   = (const float*)d_in[1];   // (N, N)
    const float* a     = (const float*)d_in[2];   // (2C, 1)
    float* out = (float*)d_out;                   // (B, N, C)

    gat_scores_kernel<<<(GB * GN) / 8, 256>>>(input, a);

    cudaFuncSetAttribute(gat_main_kernel,
                         cudaFuncAttributeMaxDynamicSharedMemorySize, DSMEM_BYTES);
    dim3 grid(GN / TI, GB);
    gat_main_kernel<<<grid, 256, DSMEM_BYTES>>>(adj, out);
}